// round 13
// baseline (speedup 1.0000x reference)
#include <cuda_runtime.h>
#include <stdint.h>

// SpikeFP32Embedding: out[t, :, :] = weight_pulse[token_ids[t], :, :]
// token_ids: [8*2048] int32; weight_pulse: [32768, 128, 32] f32; out: [16384, 128, 32] f32
// Row = 4096 f32 = 1024 float4 = 16 KB.
//
// Block-shape curve completion: 512 threads x 2 float4/thread (MLP_p1=2).
// Measured so far: 128x8 (MLP8) 77.25us < 256x4 (MLP4) 74.75us; the B300
// cross-CTA L1tex-queue spread model predicts lower front-batching reduces
// contention — this probes the MLP2 end of the curve.

static constexpr int ROW_FLOAT4 = 1024;   // float4 per row
static constexpr int THREADS    = 512;
static constexpr int PER_THREAD = ROW_FLOAT4 / THREADS;  // 2

__global__ __launch_bounds__(THREADS, 4)
void spike_embed_gather(const int* __restrict__ tok,
                        const float4* __restrict__ pulse,
                        float4* __restrict__ out)
{
    const int t = blockIdx.x;
    const int row = __ldg(tok + t);

    const float4* __restrict__ src = pulse + (size_t)row * ROW_FLOAT4 + threadIdx.x;
    float4* __restrict__ dst = out + (size_t)t * ROW_FLOAT4 + threadIdx.x;

    float4 v[PER_THREAD];
#pragma unroll
    for (int i = 0; i < PER_THREAD; ++i)
        v[i] = __ldg(src + i * THREADS);

#pragma unroll
    for (int i = 0; i < PER_THREAD; ++i)
        __stcs(dst + i * THREADS, v[i]);
}

extern "C" void kernel_launch(void* const* d_in, const int* in_sizes, int n_in,
                              void* d_out, int out_size)
{
    const int*    tok   = (const int*)d_in[0];       // [16384]
    const float4* pulse = (const float4*)d_in[1];    // [32768*1024] float4
    float4*       out   = (float4*)d_out;

    const int n_tokens = in_sizes[0];                // 16384
    spike_embed_gather<<<n_tokens, THREADS>>>(tok, pulse, out);
}

// round 14
// speedup vs baseline: 1.0039x; 1.0039x over previous
#include <cuda_runtime.h>
#include <stdint.h>

// SpikeFP32Embedding: out[t, :, :] = weight_pulse[token_ids[t], :, :]
// token_ids: [8*2048] int32; weight_pulse: [32768, 128, 32] f32; out: [16384, 128, 32] f32
// Row = 128*32 floats = 4096 f32 = 1024 float4 = 16 KB.
//
// FINAL (converged, 13 rounds). One CTA per token, 256 threads, 4 float4
// loads batched then 4 streaming stores. Moves the traffic floor (~203MB
// unique-row reads + 256MB mandatory writes = 459MB) at ~6.15 TB/s — the
// measured GB300 effective DRAM ceiling for this 56/44 read/write mix.
//
// Complete experiment log (all vs this baseline, kernel time):
//   counting-sort token dedup      +35us overhead, duplicates already L2-hit
//   L2::evict_last reads           78.4us (L2 thrash)
//   default write-back stores      neutral (75.0us)
//   persistent pipelined CTAs      78.0us (occupancy/serialization)
//   TMA bulk-copy smem ring        79.1us (path-equivalent at LTS cap)
//   2 tokens per CTA               neutral (75.5us)
//   128 thr x 8 float4 (MLP8)      77.3us (L1tex-queue contention)
//   512 thr x 2 float4 (MLP2)      75.7us (insufficient per-warp MLP)
//   256 thr x 4 float4 (MLP4)      74.75us  <- optimum

static constexpr int ROW_FLOAT4 = 1024;   // float4 per row
static constexpr int THREADS    = 256;
static constexpr int PER_THREAD = ROW_FLOAT4 / THREADS;  // 4

__global__ __launch_bounds__(THREADS, 8)
void spike_embed_gather(const int* __restrict__ tok,
                        const float4* __restrict__ pulse,
                        float4* __restrict__ out)
{
    const int t = blockIdx.x;
    const int row = __ldg(tok + t);

    const float4* __restrict__ src = pulse + (size_t)row * ROW_FLOAT4 + threadIdx.x;
    float4* __restrict__ dst = out + (size_t)t * ROW_FLOAT4 + threadIdx.x;

    float4 v[PER_THREAD];
#pragma unroll
    for (int i = 0; i < PER_THREAD; ++i)
        v[i] = __ldg(src + i * THREADS);

#pragma unroll
    for (int i = 0; i < PER_THREAD; ++i)
        __stcs(dst + i * THREADS, v[i]);
}

extern "C" void kernel_launch(void* const* d_in, const int* in_sizes, int n_in,
                              void* d_out, int out_size)
{
    const int*    tok   = (const int*)d_in[0];       // [16384]
    const float4* pulse = (const float4*)d_in[1];    // [32768*1024] float4
    float4*       out   = (float4*)d_out;

    const int n_tokens = in_sizes[0];                // 16384
    spike_embed_gather<<<n_tokens, THREADS>>>(tok, pulse, out);
}